// round 14
// baseline (speedup 1.0000x reference)
#include <cuda_runtime.h>
#include <cuda_bf16.h>
#include <stdint.h>
#include <math.h>

// Problem constants
#define Bq      2
#define Sq      2048
#define HIDq    2048
#define Hh      32
#define HKVq    8
#define DHq     64
#define GROUPSq 4
#define SCALEq  0.125f   // 64^-0.5

// ---------------------------------------------------------------------------
// Scratch (static device globals; no allocation allowed)
// ---------------------------------------------------------------------------
__device__ float g_q[Bq * Hh  * Sq * DHq];   // [B,H,S,D] fp32 (pre-RoPE)
__device__ float g_k[Bq * HKVq * Sq * DHq];
__device__ float g_v[Bq * HKVq * Sq * DHq];

// bf16 hi/lo split buffers for GEMMs (uint4 = 8 bf16)
__device__ uint4 g_hid_h[1048576], g_hid_l[1048576];   // 4096x2048
__device__ uint4 g_wq_h [524288],  g_wq_l [524288];
__device__ uint4 g_wk_h [131072],  g_wk_l [131072];
__device__ uint4 g_wv_h [131072],  g_wv_l [131072];
__device__ uint4 g_wo_h [524288],  g_wo_l [524288];
__device__ uint4 g_ao_h[1048576],  g_ao_l[1048576];    // attn out, [B*S, 2048] bf16

// bf16 hi/lo split buffers for attention (RoPE + scale folded for Q)
__device__ uint4 g_qh4[1048576], g_ql4[1048576];   // [B,H,S,64]
__device__ uint4 g_kh4[262144],  g_kl4[262144];    // [B,HKV,S,64]
__device__ uint4 g_vh4[262144],  g_vl4[262144];

// ---------------------------------------------------------------------------
// Helpers
// ---------------------------------------------------------------------------
__device__ __forceinline__ uint32_t smem_u32(const void* p) {
    uint32_t a;
    asm("{ .reg .u64 t; cvta.to.shared.u64 t, %1; cvt.u32.u64 %0, t; }"
        : "=r"(a) : "l"(p));
    return a;
}

__device__ __forceinline__ uint32_t pack_bf2(float a, float b) {
    uint32_t r;
    asm("cvt.rn.bf16x2.f32 %0, %1, %2;" : "=r"(r) : "f"(b), "f"(a));
    return r;
}

__device__ __forceinline__ void split2(float a, float b, uint32_t& h, uint32_t& l) {
    h = pack_bf2(a, b);
    const float ra = a - __uint_as_float(h << 16);
    const float rb = b - __uint_as_float(h & 0xffff0000u);
    l = pack_bf2(ra, rb);
}

__device__ __forceinline__ void ldsm_x4(uint32_t* r, uint32_t addr) {
    asm volatile("ldmatrix.sync.aligned.m8n8.x4.shared.b16 {%0,%1,%2,%3}, [%4];"
                 : "=r"(r[0]), "=r"(r[1]), "=r"(r[2]), "=r"(r[3]) : "r"(addr));
}

__device__ __forceinline__ void ldsm_x4_t(uint32_t* r, uint32_t addr) {
    asm volatile("ldmatrix.sync.aligned.m8n8.x4.trans.shared.b16 {%0,%1,%2,%3}, [%4];"
                 : "=r"(r[0]), "=r"(r[1]), "=r"(r[2]), "=r"(r[3]) : "r"(addr));
}

__device__ __forceinline__ void mma_bf16(float* c, const uint32_t* a,
                                         uint32_t b0, uint32_t b1) {
    asm volatile(
        "mma.sync.aligned.m16n8k16.row.col.f32.bf16.bf16.f32 "
        "{%0,%1,%2,%3}, {%4,%5,%6,%7}, {%8,%9}, {%0,%1,%2,%3};"
        : "+f"(c[0]), "+f"(c[1]), "+f"(c[2]), "+f"(c[3])
        : "r"(a[0]), "r"(a[1]), "r"(a[2]), "r"(a[3]), "r"(b0), "r"(b1));
}

__device__ __forceinline__ void cp16(uint32_t s, const void* g) {
    asm volatile("cp.async.cg.shared.global [%0], [%1], 16;" :: "r"(s), "l"(g));
}
#define CP_COMMIT() asm volatile("cp.async.commit_group;")
#define CP_WAIT1()  asm volatile("cp.async.wait_group 1;")
#define CP_WAIT0()  asm volatile("cp.async.wait_group 0;")

#define SWZ(x)   ((x) ^ (((x) >> 3) & 0x70))   // 128B rows
#define SWZ64(x) ((x) ^ (((x) >> 3) & 0x30))   // 64B rows

// ---------------------------------------------------------------------------
// fp32 -> bf16 hi/lo split kernel. 4 float4 per thread (MLP=4).
// Grid: n4 / 1024 blocks of 256 threads.
// ---------------------------------------------------------------------------
__global__ __launch_bounds__(256)
void split_kernel(const float4* __restrict__ in, uint2* __restrict__ hi,
                  uint2* __restrict__ lo, int n4)
{
    const int base = blockIdx.x * 1024 + threadIdx.x;
    float4 x[4];
#pragma unroll
    for (int j = 0; j < 4; j++) {
        const int i = base + j * 256;
        if (i < n4) x[j] = in[i];
    }
#pragma unroll
    for (int j = 0; j < 4; j++) {
        const int i = base + j * 256;
        if (i < n4) {
            uint32_t h0, l0, h1, l1;
            split2(x[j].x, x[j].y, h0, l0);
            split2(x[j].z, x[j].w, h1, l1);
            hi[i] = make_uint2(h0, h1);
            lo[i] = make_uint2(l0, l1);
        }
    }
}

// ---------------------------------------------------------------------------
// Fused RoPE + (optional scale) + bf16 hi/lo split
// ---------------------------------------------------------------------------
__global__ __launch_bounds__(256)
void rope_split_kernel(const float* __restrict__ x, const float* __restrict__ cosb,
                       const float* __restrict__ sinb, __nv_bfloat16* __restrict__ hi,
                       __nv_bfloat16* __restrict__ lo, int nh, float prescale)
{
    const int idx = blockIdx.x * blockDim.x + threadIdx.x;
    const int total = Bq * Sq * 32 * nh;
    if (idx >= total) return;
    const int d = idx & 31;
    const int s = (idx >> 5) & 2047;
    const int rest = idx >> 16;
    const int h = rest % nh;
    const int b = rest / nh;

    const size_t base = (((size_t)(b * nh + h)) * Sq + s) * DHq;
    const float c  = cosb[((size_t)b * Sq + s) * DHq + d];
    const float sn = sinb[((size_t)b * Sq + s) * DHq + d];
    const float x1 = x[base + d];
    const float x2 = x[base + d + 32];
    const float y1 = (x1 * c - x2 * sn) * prescale;
    const float y2 = (x2 * c + x1 * sn) * prescale;

    const __nv_bfloat16 h1 = __float2bfloat16(y1);
    const __nv_bfloat16 h2 = __float2bfloat16(y2);
    hi[base + d]      = h1;
    hi[base + d + 32] = h2;
    lo[base + d]      = __float2bfloat16(y1 - __bfloat162float(h1));
    lo[base + d + 32] = __float2bfloat16(y2 - __bfloat162float(h2));
}

// ---------------------------------------------------------------------------
// HMMA split-bf16 GEMM core. Tile 128x128, KC=32 per stage, 3-stage cp.async
// ring (96KB smem), single __syncthreads per iteration.
// ---------------------------------------------------------------------------
#define GEMM_SMEM (3 * 32768)

struct GemmAcc { float c[4][4][4]; };

__device__ __forceinline__ void gemm_mainloop(
    const uint4* __restrict__ Ah, const uint4* __restrict__ Al,
    const uint4* __restrict__ Bh, const uint4* __restrict__ Bl,
    int bm, int bn, char* sm, GemmAcc& A)
{
    const int tid = threadIdx.x;
    const int wid = tid >> 5, lid = tid & 31;
    const uint32_t sb = smem_u32(sm);

    uint32_t so2[2];
    size_t gA[2], gB[2];
#pragma unroll
    for (int i = 0; i < 2; i++) {
        const int f = tid + i * 256;
        const int row = f >> 2;
        const int c16 = f & 3;
        so2[i] = SWZ64((uint32_t)(row * 64 + c16 * 16));
        gA[i] = (size_t)(bm + row) * 256 + c16;
        gB[i] = (size_t)(bn + row) * 256 + c16;
    }

    const int wm = wid & 1;
    const int wn = wid >> 1;
    const int sub = lid >> 3, r8 = lid & 7;

    uint32_t aRow[4], aMask[4];
#pragma unroll
    for (int mt = 0; mt < 4; mt++) {
        const uint32_t rb = (uint32_t)(wm * 64 + mt * 16 + r8 + (sub & 1) * 8);
        aRow[mt] = rb * 64;
        aMask[mt] = (rb & 6) << 3;
    }
    const uint32_t aK = (uint32_t)((sub >> 1) * 16);

    uint32_t bRow[2], bMask[2];
#pragma unroll
    for (int ntp = 0; ntp < 2; ntp++) {
        const uint32_t rb = (uint32_t)(wn * 32 + ntp * 16 + r8 + (sub >> 1) * 8);
        bRow[ntp] = rb * 64;
        bMask[ntp] = (rb & 6) << 3;
    }
    const uint32_t bK = (uint32_t)((sub & 1) * 16);

#pragma unroll
    for (int i = 0; i < 4; i++)
#pragma unroll
        for (int j = 0; j < 4; j++)
#pragma unroll
            for (int k = 0; k < 4; k++) A.c[i][j][k] = 0.f;

    auto load_stage = [&](int kc, int st) {
        const uint32_t base = (uint32_t)(st * 32768);
#pragma unroll
        for (int i = 0; i < 2; i++) {
            const size_t ga = gA[i] + kc * 4;
            const size_t gb = gB[i] + kc * 4;
            cp16(sb + base + 0     + so2[i], Ah + ga);
            cp16(sb + base + 8192  + so2[i], Al + ga);
            cp16(sb + base + 16384 + so2[i], Bh + gb);
            cp16(sb + base + 24576 + so2[i], Bl + gb);
        }
    };

    // 3-stage ring. FIFO group retire => wait_group(1) at iter kc guarantees
    // stage kc resident (only the newest group may still be pending).
    load_stage(0, 0);
    CP_COMMIT();
    load_stage(1, 1);
    CP_COMMIT();

    int st_r = 0, st_w = 2;
    for (int kc = 0; kc < 64; kc++) {
        if (kc < 63) { CP_WAIT1(); } else { CP_WAIT0(); }
        __syncthreads();   // all threads done with stage (kc-1) and see stage kc

        if (kc + 2 < 64) {
            load_stage(kc + 2, st_w);
            CP_COMMIT();
            if (++st_w == 3) st_w = 0;
        }

        const uint32_t base = sb + (uint32_t)(st_r * 32768);
        if (++st_r == 3) st_r = 0;
#pragma unroll
        for (int ks = 0; ks < 2; ks++) {
            const uint32_t kb = (uint32_t)(ks * 32);
            uint32_t ah[4][4], al[4][4], bh[2][4], bl[2][4];
#pragma unroll
            for (int mt = 0; mt < 4; mt++) {
                const uint32_t ko = (kb + aK) ^ aMask[mt];
                ldsm_x4(ah[mt], base + 0    + aRow[mt] + ko);
                ldsm_x4(al[mt], base + 8192 + aRow[mt] + ko);
            }
#pragma unroll
            for (int ntp = 0; ntp < 2; ntp++) {
                const uint32_t ko = (kb + bK) ^ bMask[ntp];
                ldsm_x4(bh[ntp], base + 16384 + bRow[ntp] + ko);
                ldsm_x4(bl[ntp], base + 24576 + bRow[ntp] + ko);
            }
#pragma unroll
            for (int mt = 0; mt < 4; mt++)
#pragma unroll
                for (int ntp = 0; ntp < 2; ntp++)
#pragma unroll
                    for (int h = 0; h < 2; h++) {
                        float* acc = A.c[mt][ntp * 2 + h];
                        mma_bf16(acc, ah[mt], bh[ntp][h * 2], bh[ntp][h * 2 + 1]);
                        mma_bf16(acc, ah[mt], bl[ntp][h * 2], bl[ntp][h * 2 + 1]);
                        mma_bf16(acc, al[mt], bh[ntp][h * 2], bh[ntp][h * 2 + 1]);
                    }
        }
    }
    __syncthreads();
}

// Fused QKV projection: grid (24, 32). x-regions: [0,16)=Q, [16,20)=K, [20,24)=V.
__global__ __launch_bounds__(256)
void hgemm_qkv_kernel(const uint4* __restrict__ Ah, const uint4* __restrict__ Al,
                      const uint4* __restrict__ Wqh, const uint4* __restrict__ Wql,
                      const uint4* __restrict__ Wkh, const uint4* __restrict__ Wkl,
                      const uint4* __restrict__ Wvh, const uint4* __restrict__ Wvl,
                      float* __restrict__ Cq, float* __restrict__ Ck,
                      float* __restrict__ Cv)
{
    extern __shared__ __align__(1024) char sm[];
    const int bnr = blockIdx.x;
    const int bm = blockIdx.y * 128;

    const uint4 *Bh, *Bl;
    float* C;
    int Hout, bnl;
    if (bnr < 16)      { Bh = Wqh; Bl = Wql; C = Cq; Hout = Hh;   bnl = bnr * 128; }
    else if (bnr < 20) { Bh = Wkh; Bl = Wkl; C = Ck; Hout = HKVq; bnl = (bnr - 16) * 128; }
    else               { Bh = Wvh; Bl = Wvl; C = Cv; Hout = HKVq; bnl = (bnr - 20) * 128; }

    GemmAcc A;
    gemm_mainloop(Ah, Al, Bh, Bl, bm, bnl, sm, A);

    const int wid = threadIdx.x >> 5, lid = threadIdx.x & 31;
    const int wm = wid & 1, wn = wid >> 1;
    const int g = lid >> 2, t = lid & 3;
#pragma unroll
    for (int mt = 0; mt < 4; mt++) {
#pragma unroll
        for (int nt = 0; nt < 4; nt++) {
            const int row0 = bm + wm * 64 + mt * 16 + g;
            const int col0 = bnl + wn * 32 + nt * 8 + t * 2;
#pragma unroll
            for (int rh = 0; rh < 2; rh++) {
                const int m = row0 + rh * 8;
                float2 val = make_float2(A.c[mt][nt][rh * 2], A.c[mt][nt][rh * 2 + 1]);
                const int b = m >> 11, s = m & 2047;
                const int h = col0 >> 6, d0 = col0 & 63;
                *(float2*)&C[(((size_t)(b * Hout + h)) * Sq + s) * DHq + d0] = val;
            }
        }
    }
}

// Row-major GEMM for the output projection.
__global__ __launch_bounds__(256)
void hgemm_kernel(const uint4* __restrict__ Ah, const uint4* __restrict__ Al,
                  const uint4* __restrict__ Bh, const uint4* __restrict__ Bl,
                  float* __restrict__ C, int N)
{
    extern __shared__ __align__(1024) char sm[];
    const int bm = blockIdx.y * 128, bn = blockIdx.x * 128;

    GemmAcc A;
    gemm_mainloop(Ah, Al, Bh, Bl, bm, bn, sm, A);

    const int wid = threadIdx.x >> 5, lid = threadIdx.x & 31;
    const int wm = wid & 1, wn = wid >> 1;
    const int g = lid >> 2, t = lid & 3;
#pragma unroll
    for (int mt = 0; mt < 4; mt++) {
#pragma unroll
        for (int nt = 0; nt < 4; nt++) {
            const int row0 = bm + wm * 64 + mt * 16 + g;
            const int col0 = bn + wn * 32 + nt * 8 + t * 2;
#pragma unroll
            for (int rh = 0; rh < 2; rh++) {
                const int m = row0 + rh * 8;
                *(float2*)&C[(size_t)m * N + col0] =
                    make_float2(A.c[mt][nt][rh * 2], A.c[mt][nt][rh * 2 + 1]);
            }
        }
    }
}

// ---------------------------------------------------------------------------
// HMMA flash attention, split-bf16, cp.async double-buffered (unchanged).
// Block 256 threads (8 warps), Q-tile 128 (warp = 16 rows), K-tile 64.
// ---------------------------------------------------------------------------
#define FMHA_SMEM (2 * 32768)

__global__ __launch_bounds__(256)
void fmha_kernel(const uint4* __restrict__ Qh4, const uint4* __restrict__ Ql4,
                 const uint4* __restrict__ Kh4, const uint4* __restrict__ Kl4,
                 const uint4* __restrict__ Vh4, const uint4* __restrict__ Vl4,
                 uint32_t* __restrict__ oh, uint32_t* __restrict__ ol)
{
    extern __shared__ __align__(1024) char smf[];
    const uint32_t sb = smem_u32(smf);

    const int tid = threadIdx.x;
    const int wid = tid >> 5, lid = tid & 31;
    const int qt = (int)gridDim.x - 1 - (int)blockIdx.x;   // longest first
    const int h = blockIdx.y, b = blockIdx.z;
    const int kvh = h >> 2;

    const int g = lid >> 2, t = lid & 3;
    const int r8 = lid & 7, sub = lid >> 3;

    // Q fragments: warp covers rows [qt*128 + wid*16, +16)
    const uint32_t* Qh = (const uint32_t*)Qh4;
    const uint32_t* Ql = (const uint32_t*)Ql4;
    const size_t qbase = ((size_t)(b * Hh + h) * Sq) * 32;
    const int row0 = qt * 128 + wid * 16 + g;
    uint32_t qa_h[4][4], qa_l[4][4];
#pragma unroll
    for (int j = 0; j < 4; j++) {
        const size_t b0 = qbase + (size_t)row0 * 32 + j * 8 + t;
        const size_t b1 = b0 + 8 * 32;
        qa_h[j][0] = Qh[b0];     qa_h[j][1] = Qh[b1];
        qa_h[j][2] = Qh[b0 + 4]; qa_h[j][3] = Qh[b1 + 4];
        qa_l[j][0] = Ql[b0];     qa_l[j][1] = Ql[b1];
        qa_l[j][2] = Ql[b0 + 4]; qa_l[j][3] = Ql[b1 + 4];
    }

    const size_t kb4 = ((size_t)(b * HKVq + kvh) * Sq) * 8;

    uint32_t so2[2];
    size_t gk[2];
#pragma unroll
    for (int i = 0; i < 2; i++) {
        const int f = tid + i * 256;
        const int row = f >> 3, c16 = f & 7;
        so2[i] = SWZ((uint32_t)(row * 128 + c16 * 16));
        gk[i] = (size_t)row * 8 + c16;
    }

    auto load_stage = [&](int jt, int st) {
        const uint32_t base = (uint32_t)(st * 32768);
        const size_t gbase = kb4 + (size_t)jt * 64 * 8;
#pragma unroll
        for (int i = 0; i < 2; i++) {
            const size_t gi = gbase + gk[i];
            cp16(sb + base + 0     + so2[i], Kh4 + gi);
            cp16(sb + base + 8192  + so2[i], Kl4 + gi);
            cp16(sb + base + 16384 + so2[i], Vh4 + gi);
            cp16(sb + base + 24576 + so2[i], Vl4 + gi);
        }
    };

    float m0 = -1e30f, m1 = -1e30f, l0 = 0.f, l1 = 0.f;
    float o_[8][4];
#pragma unroll
    for (int i = 0; i < 8; i++)
#pragma unroll
        for (int k = 0; k < 4; k++) o_[i][k] = 0.f;

    const int jtmax = 2 * qt + 1;

    load_stage(0, 0);
    CP_COMMIT();

    for (int jt = 0; jt <= jtmax; jt++) {
        if (jt < jtmax) {
            load_stage(jt + 1, (jt + 1) & 1);
            CP_COMMIT();
            CP_WAIT1();
        } else {
            CP_WAIT0();
        }
        __syncthreads();

        const uint32_t base = sb + (uint32_t)((jt & 1) * 32768);
        const uint32_t skh = base, skl = base + 8192;
        const uint32_t svh = base + 16384, svl = base + 24576;

        // ---- S = Q K^T ----
        float s[8][4];
#pragma unroll
        for (int i = 0; i < 8; i++)
#pragma unroll
            for (int k = 0; k < 4; k++) s[i][k] = 0.f;

#pragma unroll
        for (int j = 0; j < 4; j++) {
#pragma unroll
            for (int nb = 0; nb < 4; nb++) {
                const int row = nb * 16 + r8 + ((sub >> 1) << 3);
                const uint32_t colb = (uint32_t)(j * 32 + ((sub & 1) << 4));
                const uint32_t ad = (uint32_t)(row * 128) + (colb ^ (uint32_t)((row & 7) << 4));
                uint32_t kh[4], kl[4];
                ldsm_x4(kh, skh + ad);
                ldsm_x4(kl, skl + ad);
#pragma unroll
                for (int hh = 0; hh < 2; hh++) {
                    float* acc = s[nb * 2 + hh];
                    mma_bf16(acc, qa_h[j], kh[hh * 2], kh[hh * 2 + 1]);
                    mma_bf16(acc, qa_h[j], kl[hh * 2], kl[hh * 2 + 1]);
                    mma_bf16(acc, qa_l[j], kh[hh * 2], kh[hh * 2 + 1]);
                }
            }
        }

        // ---- causal mask (near-diagonal tiles; also zeroes fully-masked) ----
        if (jt * 64 + 63 > row0) {
#pragma unroll
            for (int nt = 0; nt < 8; nt++) {
                const int col = jt * 64 + nt * 8 + t * 2;
                if (col     > row0)     s[nt][0] = -1e30f;
                if (col + 1 > row0)     s[nt][1] = -1e30f;
                if (col     > row0 + 8) s[nt][2] = -1e30f;
                if (col + 1 > row0 + 8) s[nt][3] = -1e30f;
            }
        }

        // ---- online softmax ----
        float mx0 = -1e30f, mx1 = -1e30f;
#pragma unroll
        for (int nt = 0; nt < 8; nt++) {
            mx0 = fmaxf(mx0, fmaxf(s[nt][0], s[nt][1]));
            mx1 = fmaxf(mx1, fmaxf(s[nt][2], s[nt][3]));
        }
        mx0 = fmaxf(mx0, __shfl_xor_sync(0xffffffffu, mx0, 1));
        mx0 = fmaxf(mx0, __shfl_xor_sync(0xffffffffu, mx0, 2));
        mx1 = fmaxf(mx1, __shfl_xor_sync(0xffffffffu, mx1, 1));
        mx1 = fmaxf(mx1, __shfl_xor_sync(0xffffffffu, mx1, 2));

        const float m0n = fmaxf(m0, mx0), m1n = fmaxf(m1, mx1);
        const float f0 = __expf(m0 - m0n), f1 = __expf(m1 - m1n);

        float sum0 = 0.f, sum1 = 0.f;
#pragma unroll
        for (int nt = 0; nt < 8; nt++) {
            s[nt][0] = __expf(s[nt][0] - m0n); sum0 += s[nt][0];
            s[nt][1] = __expf(s[nt][1] - m0n); sum0 += s[nt][1];
            s[nt][2] = __expf(s[nt][2] - m1n); sum1 += s[nt][2];
            s[nt][3] = __expf(s[nt][3] - m1n); sum1 += s[nt][3];
        }
        sum0 += __shfl_xor_sync(0xffffffffu, sum0, 1);
        sum0 += __shfl_xor_sync(0xffffffffu, sum0, 2);
        sum1 += __shfl_xor_sync(0xffffffffu, sum1, 1);
        sum1 += __shfl_xor_sync(0xffffffffu, sum1, 2);

        l0 = l0 * f0 + sum0;
        l1 = l1 * f1 + sum1;
        m0 = m0n; m1 = m1n;
#pragma unroll
        for (int dt = 0; dt < 8; dt++) {
            o_[dt][0] *= f0; o_[dt][1] *= f0;
            o_[dt][2] *= f1; o_[dt][3] *= f1;
        }

        // ---- pack P fragments (hi/lo) ----
        uint32_t ph[4][4], pl[4][4];
#pragma unroll
        for (int j = 0; j < 4; j++) {
            split2(s[2 * j][0],     s[2 * j][1],     ph[j][0], pl[j][0]);
            split2(s[2 * j][2],     s[2 * j][3],     ph[j][1], pl[j][1]);
            split2(s[2 * j + 1][0], s[2 * j + 1][1], ph[j][2], pl[j][2]);
            split2(s[2 * j + 1][2], s[2 * j + 1][3], ph[j][3], pl[j][3]);
        }

        // ---- O += P V ----
#pragma unroll
        for (int j = 0; j < 4; j++) {
#pragma unroll
            for (int db = 0; db < 4; db++) {
                const int row = 16 * j + r8 + ((sub & 1) << 3);
                const uint32_t colb = (uint32_t)(db * 32 + ((sub >> 1) << 4));
                const uint32_t ad = (uint32_t)(row * 128) + (colb ^ (uint32_t)((row & 7) << 4));
                uint32_t vh[4], vl[4];
                ldsm_x4_t(vh, svh + ad);
                ldsm_x4_t(vl, svl + ad);
#pragma unroll
                for (int hh = 0; hh < 2; hh++) {
                    float* acc = o_[db * 2 + hh];
                    mma_bf16(acc, ph[j], vh[hh * 2], vh[hh * 2 + 1]);
                    mma_bf16(acc, ph[j], vl[hh * 2], vl[hh * 2 + 1]);
                    mma_bf16(acc, pl[j], vh[hh * 2], vh[hh * 2 + 1]);
                }
            }
        }
        __syncthreads();
    }

    // ---- epilogue: O /= l, split to bf16 hi/lo, write [B*S, 2048] ----
    const float inv0 = 1.f / l0, inv1 = 1.f / l1;
    const size_t r0u = ((size_t)b * Sq + row0) * 1024 + h * 32;
    const size_t r1u = r0u + (size_t)8 * 1024;
#pragma unroll
    for (int dt = 0; dt < 8; dt++) {
        const int du = (dt * 8 + t * 2) >> 1;
        uint32_t hh, ll;
        split2(o_[dt][0] * inv0, o_[dt][1] * inv0, hh, ll);
        oh[r0u + du] = hh; ol[r0u + du] = ll;
        split2(o_[dt][2] * inv1, o_[dt][3] * inv1, hh, ll);
        oh[r1u + du] = hh; ol[r1u + du] = ll;
    }
}

// ---------------------------------------------------------------------------
// Launch
// ---------------------------------------------------------------------------
extern "C" void kernel_launch(void* const* d_in, const int* in_sizes, int n_in,
                              void* d_out, int out_size)
{
    const float* hidden = (const float*)d_in[0];
    const float* cosb   = (const float*)d_in[1];
    const float* sinb   = (const float*)d_in[2];
    // d_in[3] = attention_mask (pure causal; not needed)
    float* out = (float*)d_out;

    cudaFuncSetAttribute(hgemm_qkv_kernel, cudaFuncAttributeMaxDynamicSharedMemorySize, GEMM_SMEM);
    cudaFuncSetAttribute(hgemm_kernel, cudaFuncAttributeMaxDynamicSharedMemorySize, GEMM_SMEM);
    cudaFuncSetAttribute(fmha_kernel, cudaFuncAttributeMaxDynamicSharedMemorySize, FMHA_SMEM);

    float *qp, *kp, *vp;
    cudaGetSymbolAddress((void**)&qp, g_q);
    cudaGetSymbolAddress((void**)&kp, g_k);
    cudaGetSymbolAddress((void**)&vp, g_v);

    uint4 *hidh, *hidl, *wqh, *wql, *wkh, *wkl, *wvh, *wvl, *woh, *wol, *aoh, *aol;
    cudaGetSymbolAddress((void**)&hidh, g_hid_h); cudaGetSymbolAddress((void**)&hidl, g_hid_l);
    cudaGetSymbolAddress((void**)&wqh,  g_wq_h);  cudaGetSymbolAddress((void**)&wql,  g_wq_l);
    cudaGetSymbolAddress((void**)&wkh,  g_wk_h);  cudaGetSymbolAddress((void**)&wkl,  g_wk_l);
    cudaGetSymbolAddress((void**)&wvh,  g_wv_h);  cudaGetSymbolAddress((void**)&wvl,  g_wv_l);
    cudaGetSymbolAddress((void**)&woh,  g_wo_h);  cudaGetSymbolAddress((void**)&wol,  g_wo_l);
    cudaGetSymbolAddress((void**)&aoh,  g_ao_h);  cudaGetSymbolAddress((void**)&aol,  g_ao_l);

    uint4 *qh, *ql, *kh, *kl, *vh, *vl;
    cudaGetSymbolAddress((void**)&qh, g_qh4); cudaGetSymbolAddress((void**)&ql, g_ql4);
    cudaGetSymbolAddress((void**)&kh, g_kh4); cudaGetSymbolAddress((void**)&kl, g_kl4);
    cudaGetSymbolAddress((void**)&vh, g_vh4); cudaGetSymbolAddress((void**)&vl, g_vl4);

    // Split inputs/weights to bf16 hi/lo (4 float4 per thread)
    split_kernel<<<2048, 256>>>((const float4*)hidden,  (uint2*)hidh, (uint2*)hidl, 2097152);
    split_kernel<<<1024, 256>>>((const float4*)d_in[4], (uint2*)wqh,  (uint2*)wql,  1048576);
    split_kernel<<<256,  256>>>((const float4*)d_in[5], (uint2*)wkh,  (uint2*)wkl,   262144);
    split_kernel<<<256,  256>>>((const float4*)d_in[6], (uint2*)wvh,  (uint2*)wvl,   262144);
    split_kernel<<<1024, 256>>>((const float4*)d_in[7], (uint2*)woh,  (uint2*)wol,  1048576);

    // Fused QKV projection (one launch) -> [B,H,S,D] fp32
    hgemm_qkv_kernel<<<dim3(24, 32), 256, GEMM_SMEM>>>(
        hidh, hidl, wqh, wql, wkh, wkl, wvh, wvl, qp, kp, vp);

    // Fused RoPE (+softmax scale for Q) + bf16 hi/lo pack; V plain split
    rope_split_kernel<<<(Bq * Hh  * Sq * 32 + 255) / 256, 256>>>(
        qp, cosb, sinb, (__nv_bfloat16*)qh, (__nv_bfloat16*)ql, Hh, SCALEq);
    rope_split_kernel<<<(Bq * HKVq * Sq * 32 + 255) / 256, 256>>>(
        kp, cosb, sinb, (__nv_bfloat16*)kh, (__nv_bfloat16*)kl, HKVq, 1.0f);
    split_kernel<<<512, 256>>>((const float4*)vp, (uint2*)vh, (uint2*)vl, 524288);

    // HMMA flash attention (Q-tile 128, reversed order) -> bf16 hi/lo attn out
    fmha_kernel<<<dim3(16, Hh, Bq), 256, FMHA_SMEM>>>(qh, ql, kh, kl, vh, vl,
                                                      (uint32_t*)aoh, (uint32_t*)aol);

    // Output projection on tensor cores -> d_out
    hgemm_kernel<<<dim3(16, 32), 256, GEMM_SMEM>>>(aoh, aol, woh, wol, out, 2048);
}

// round 15
// speedup vs baseline: 1.0510x; 1.0510x over previous
#include <cuda_runtime.h>
#include <cuda_bf16.h>
#include <stdint.h>
#include <math.h>

// Problem constants
#define Bq      2
#define Sq      2048
#define HIDq    2048
#define Hh      32
#define HKVq    8
#define DHq     64
#define GROUPSq 4
#define SCALEq  0.125f   // 64^-0.5

// ---------------------------------------------------------------------------
// Scratch (static device globals; no allocation allowed)
// ---------------------------------------------------------------------------
__device__ float g_q[Bq * Hh  * Sq * DHq];   // [B,H,S,D] fp32 (pre-RoPE)
__device__ float g_k[Bq * HKVq * Sq * DHq];
__device__ float g_v[Bq * HKVq * Sq * DHq];

// bf16 hi/lo split buffers for GEMMs (uint4 = 8 bf16)
__device__ uint4 g_hid_h[1048576], g_hid_l[1048576];   // 4096x2048
__device__ uint4 g_wq_h [524288],  g_wq_l [524288];
__device__ uint4 g_wk_h [131072],  g_wk_l [131072];
__device__ uint4 g_wv_h [131072],  g_wv_l [131072];
__device__ uint4 g_wo_h [524288],  g_wo_l [524288];
__device__ uint4 g_ao_h[1048576],  g_ao_l[1048576];    // attn out, [B*S, 2048] bf16

// bf16 hi/lo split buffers for attention (RoPE + scale folded for Q)
__device__ uint4 g_qh4[1048576], g_ql4[1048576];   // [B,H,S,64]
__device__ uint4 g_kh4[262144],  g_kl4[262144];    // [B,HKV,S,64]
__device__ uint4 g_vh4[262144],  g_vl4[262144];

// ---------------------------------------------------------------------------
// Helpers
// ---------------------------------------------------------------------------
__device__ __forceinline__ uint32_t smem_u32(const void* p) {
    uint32_t a;
    asm("{ .reg .u64 t; cvta.to.shared.u64 t, %1; cvt.u32.u64 %0, t; }"
        : "=r"(a) : "l"(p));
    return a;
}

__device__ __forceinline__ uint32_t pack_bf2(float a, float b) {
    uint32_t r;
    asm("cvt.rn.bf16x2.f32 %0, %1, %2;" : "=r"(r) : "f"(b), "f"(a));
    return r;
}

__device__ __forceinline__ void split2(float a, float b, uint32_t& h, uint32_t& l) {
    h = pack_bf2(a, b);
    const float ra = a - __uint_as_float(h << 16);
    const float rb = b - __uint_as_float(h & 0xffff0000u);
    l = pack_bf2(ra, rb);
}

__device__ __forceinline__ void ldsm_x4(uint32_t* r, uint32_t addr) {
    asm volatile("ldmatrix.sync.aligned.m8n8.x4.shared.b16 {%0,%1,%2,%3}, [%4];"
                 : "=r"(r[0]), "=r"(r[1]), "=r"(r[2]), "=r"(r[3]) : "r"(addr));
}

__device__ __forceinline__ void ldsm_x4_t(uint32_t* r, uint32_t addr) {
    asm volatile("ldmatrix.sync.aligned.m8n8.x4.trans.shared.b16 {%0,%1,%2,%3}, [%4];"
                 : "=r"(r[0]), "=r"(r[1]), "=r"(r[2]), "=r"(r[3]) : "r"(addr));
}

__device__ __forceinline__ void mma_bf16(float* c, const uint32_t* a,
                                         uint32_t b0, uint32_t b1) {
    asm volatile(
        "mma.sync.aligned.m16n8k16.row.col.f32.bf16.bf16.f32 "
        "{%0,%1,%2,%3}, {%4,%5,%6,%7}, {%8,%9}, {%0,%1,%2,%3};"
        : "+f"(c[0]), "+f"(c[1]), "+f"(c[2]), "+f"(c[3])
        : "r"(a[0]), "r"(a[1]), "r"(a[2]), "r"(a[3]), "r"(b0), "r"(b1));
}

__device__ __forceinline__ void cp16(uint32_t s, const void* g) {
    asm volatile("cp.async.cg.shared.global [%0], [%1], 16;" :: "r"(s), "l"(g));
}
#define CP_COMMIT() asm volatile("cp.async.commit_group;")
#define CP_WAIT1()  asm volatile("cp.async.wait_group 1;")
#define CP_WAIT0()  asm volatile("cp.async.wait_group 0;")

#define SWZ(x)   ((x) ^ (((x) >> 3) & 0x70))   // 128B rows
#define SWZ64(x) ((x) ^ (((x) >> 3) & 0x30))   // 64B rows

// ---------------------------------------------------------------------------
// Fused 5-way fp32 -> bf16 hi/lo split. Segmented grid, 1024 float4 per
// block (4 per thread). All segment sizes are multiples of 1024.
// Segments (blocks): hid 2048 | wq 1024 | wk 256 | wv 256 | wo 1024 = 4608.
// ---------------------------------------------------------------------------
__device__ __forceinline__ void split_body(const float4* __restrict__ in,
                                           uint2* __restrict__ hi,
                                           uint2* __restrict__ lo, int lb)
{
    const int base = lb * 1024 + threadIdx.x;
    float4 x[4];
#pragma unroll
    for (int j = 0; j < 4; j++) x[j] = in[base + j * 256];
#pragma unroll
    for (int j = 0; j < 4; j++) {
        uint32_t h0, l0, h1, l1;
        split2(x[j].x, x[j].y, h0, l0);
        split2(x[j].z, x[j].w, h1, l1);
        hi[base + j * 256] = make_uint2(h0, h1);
        lo[base + j * 256] = make_uint2(l0, l1);
    }
}

__global__ __launch_bounds__(256)
void split5_kernel(const float4* __restrict__ i0, uint2* __restrict__ h0, uint2* __restrict__ l0,
                   const float4* __restrict__ i1, uint2* __restrict__ h1, uint2* __restrict__ l1,
                   const float4* __restrict__ i2, uint2* __restrict__ h2, uint2* __restrict__ l2,
                   const float4* __restrict__ i3, uint2* __restrict__ h3, uint2* __restrict__ l3,
                   const float4* __restrict__ i4, uint2* __restrict__ h4, uint2* __restrict__ l4)
{
    const int bx = blockIdx.x;
    if (bx < 2048)      split_body(i0, h0, l0, bx);
    else if (bx < 3072) split_body(i1, h1, l1, bx - 2048);
    else if (bx < 3328) split_body(i2, h2, l2, bx - 3072);
    else if (bx < 3584) split_body(i3, h3, l3, bx - 3328);
    else                split_body(i4, h4, l4, bx - 3584);
}

// ---------------------------------------------------------------------------
// Fused post-QKV: RoPE+scale+split for Q, RoPE+split for K, plain split V.
// Segments (blocks of 256 thr): Q 16384 | K 4096 | V 512 = 20992.
// ---------------------------------------------------------------------------
__device__ __forceinline__ void rope_body(const float* __restrict__ x,
                                          const float* __restrict__ cosb,
                                          const float* __restrict__ sinb,
                                          __nv_bfloat16* __restrict__ hi,
                                          __nv_bfloat16* __restrict__ lo,
                                          int nh, float prescale, int idx)
{
    const int d = idx & 31;
    const int s = (idx >> 5) & 2047;
    const int rest = idx >> 16;
    const int h = rest % nh;
    const int b = rest / nh;

    const size_t base = (((size_t)(b * nh + h)) * Sq + s) * DHq;
    const float c  = cosb[((size_t)b * Sq + s) * DHq + d];
    const float sn = sinb[((size_t)b * Sq + s) * DHq + d];
    const float x1 = x[base + d];
    const float x2 = x[base + d + 32];
    const float y1 = (x1 * c - x2 * sn) * prescale;
    const float y2 = (x2 * c + x1 * sn) * prescale;

    const __nv_bfloat16 b1 = __float2bfloat16(y1);
    const __nv_bfloat16 b2 = __float2bfloat16(y2);
    hi[base + d]      = b1;
    hi[base + d + 32] = b2;
    lo[base + d]      = __float2bfloat16(y1 - __bfloat162float(b1));
    lo[base + d + 32] = __float2bfloat16(y2 - __bfloat162float(b2));
}

__global__ __launch_bounds__(256)
void postqkv_kernel(const float* __restrict__ qp, const float* __restrict__ kp,
                    const float4* __restrict__ vp,
                    const float* __restrict__ cosb, const float* __restrict__ sinb,
                    __nv_bfloat16* __restrict__ qh, __nv_bfloat16* __restrict__ ql,
                    __nv_bfloat16* __restrict__ kh, __nv_bfloat16* __restrict__ kl,
                    uint2* __restrict__ vh, uint2* __restrict__ vl)
{
    const int bx = blockIdx.x;
    if (bx < 16384) {
        rope_body(qp, cosb, sinb, qh, ql, Hh, SCALEq, bx * 256 + threadIdx.x);
    } else if (bx < 20480) {
        rope_body(kp, cosb, sinb, kh, kl, HKVq, 1.0f, (bx - 16384) * 256 + threadIdx.x);
    } else {
        split_body(vp, vh, vl, bx - 20480);
    }
}

// ---------------------------------------------------------------------------
// HMMA split-bf16 GEMM core. Tile 128x128, KC=32, cp.async 2 stages (64KB,
// 3 CTAs/SM). Validated best configuration (R10/R11: 1059us).
// ---------------------------------------------------------------------------
#define GEMM_SMEM (2 * 32768)

struct GemmAcc { float c[4][4][4]; };

__device__ __forceinline__ void gemm_mainloop(
    const uint4* __restrict__ Ah, const uint4* __restrict__ Al,
    const uint4* __restrict__ Bh, const uint4* __restrict__ Bl,
    int bm, int bn, char* sm, GemmAcc& A)
{
    const int tid = threadIdx.x;
    const int wid = tid >> 5, lid = tid & 31;
    const uint32_t sb = smem_u32(sm);

    uint32_t so2[2];
    size_t gA[2], gB[2];
#pragma unroll
    for (int i = 0; i < 2; i++) {
        const int f = tid + i * 256;
        const int row = f >> 2;
        const int c16 = f & 3;
        so2[i] = SWZ64((uint32_t)(row * 64 + c16 * 16));
        gA[i] = (size_t)(bm + row) * 256 + c16;
        gB[i] = (size_t)(bn + row) * 256 + c16;
    }

    const int wm = wid & 1;
    const int wn = wid >> 1;
    const int sub = lid >> 3, r8 = lid & 7;

    uint32_t aRow[4], aMask[4];
#pragma unroll
    for (int mt = 0; mt < 4; mt++) {
        const uint32_t rb = (uint32_t)(wm * 64 + mt * 16 + r8 + (sub & 1) * 8);
        aRow[mt] = rb * 64;
        aMask[mt] = (rb & 6) << 3;
    }
    const uint32_t aK = (uint32_t)((sub >> 1) * 16);

    uint32_t bRow[2], bMask[2];
#pragma unroll
    for (int ntp = 0; ntp < 2; ntp++) {
        const uint32_t rb = (uint32_t)(wn * 32 + ntp * 16 + r8 + (sub >> 1) * 8);
        bRow[ntp] = rb * 64;
        bMask[ntp] = (rb & 6) << 3;
    }
    const uint32_t bK = (uint32_t)((sub & 1) * 16);

#pragma unroll
    for (int i = 0; i < 4; i++)
#pragma unroll
        for (int j = 0; j < 4; j++)
#pragma unroll
            for (int k = 0; k < 4; k++) A.c[i][j][k] = 0.f;

    auto load_stage = [&](int kc, int st) {
        const uint32_t base = (uint32_t)(st * 32768);
#pragma unroll
        for (int i = 0; i < 2; i++) {
            const size_t ga = gA[i] + kc * 4;
            const size_t gb = gB[i] + kc * 4;
            cp16(sb + base + 0     + so2[i], Ah + ga);
            cp16(sb + base + 8192  + so2[i], Al + ga);
            cp16(sb + base + 16384 + so2[i], Bh + gb);
            cp16(sb + base + 24576 + so2[i], Bl + gb);
        }
    };

    load_stage(0, 0);
    CP_COMMIT();

    for (int kc = 0; kc < 64; kc++) {
        if (kc + 1 < 64) {
            load_stage(kc + 1, (kc + 1) & 1);
            CP_COMMIT();
            CP_WAIT1();
        } else {
            CP_WAIT0();
        }
        __syncthreads();

        const uint32_t base = sb + (uint32_t)((kc & 1) * 32768);
#pragma unroll
        for (int ks = 0; ks < 2; ks++) {
            const uint32_t kb = (uint32_t)(ks * 32);
            uint32_t ah[4][4], al[4][4], bh[2][4], bl[2][4];
#pragma unroll
            for (int mt = 0; mt < 4; mt++) {
                const uint32_t ko = (kb + aK) ^ aMask[mt];
                ldsm_x4(ah[mt], base + 0    + aRow[mt] + ko);
                ldsm_x4(al[mt], base + 8192 + aRow[mt] + ko);
            }
#pragma unroll
            for (int ntp = 0; ntp < 2; ntp++) {
                const uint32_t ko = (kb + bK) ^ bMask[ntp];
                ldsm_x4(bh[ntp], base + 16384 + bRow[ntp] + ko);
                ldsm_x4(bl[ntp], base + 24576 + bRow[ntp] + ko);
            }
#pragma unroll
            for (int mt = 0; mt < 4; mt++)
#pragma unroll
                for (int ntp = 0; ntp < 2; ntp++)
#pragma unroll
                    for (int h = 0; h < 2; h++) {
                        float* acc = A.c[mt][ntp * 2 + h];
                        mma_bf16(acc, ah[mt], bh[ntp][h * 2], bh[ntp][h * 2 + 1]);
                        mma_bf16(acc, ah[mt], bl[ntp][h * 2], bl[ntp][h * 2 + 1]);
                        mma_bf16(acc, al[mt], bh[ntp][h * 2], bh[ntp][h * 2 + 1]);
                    }
        }
        __syncthreads();
    }
}

// Fused QKV projection: grid (24, 32). x-regions: [0,16)=Q, [16,20)=K, [20,24)=V.
__global__ __launch_bounds__(256)
void hgemm_qkv_kernel(const uint4* __restrict__ Ah, const uint4* __restrict__ Al,
                      const uint4* __restrict__ Wqh, const uint4* __restrict__ Wql,
                      const uint4* __restrict__ Wkh, const uint4* __restrict__ Wkl,
                      const uint4* __restrict__ Wvh, const uint4* __restrict__ Wvl,
                      float* __restrict__ Cq, float* __restrict__ Ck,
                      float* __restrict__ Cv)
{
    extern __shared__ __align__(1024) char sm[];
    const int bnr = blockIdx.x;
    const int bm = blockIdx.y * 128;

    const uint4 *Bh, *Bl;
    float* C;
    int Hout, bnl;
    if (bnr < 16)      { Bh = Wqh; Bl = Wql; C = Cq; Hout = Hh;   bnl = bnr * 128; }
    else if (bnr < 20) { Bh = Wkh; Bl = Wkl; C = Ck; Hout = HKVq; bnl = (bnr - 16) * 128; }
    else               { Bh = Wvh; Bl = Wvl; C = Cv; Hout = HKVq; bnl = (bnr - 20) * 128; }

    GemmAcc A;
    gemm_mainloop(Ah, Al, Bh, Bl, bm, bnl, sm, A);

    const int wid = threadIdx.x >> 5, lid = threadIdx.x & 31;
    const int wm = wid & 1, wn = wid >> 1;
    const int g = lid >> 2, t = lid & 3;
#pragma unroll
    for (int mt = 0; mt < 4; mt++) {
#pragma unroll
        for (int nt = 0; nt < 4; nt++) {
            const int row0 = bm + wm * 64 + mt * 16 + g;
            const int col0 = bnl + wn * 32 + nt * 8 + t * 2;
#pragma unroll
            for (int rh = 0; rh < 2; rh++) {
                const int m = row0 + rh * 8;
                float2 val = make_float2(A.c[mt][nt][rh * 2], A.c[mt][nt][rh * 2 + 1]);
                const int b = m >> 11, s = m & 2047;
                const int h = col0 >> 6, d0 = col0 & 63;
                *(float2*)&C[(((size_t)(b * Hout + h)) * Sq + s) * DHq + d0] = val;
            }
        }
    }
}

// Row-major GEMM for the output projection.
__global__ __launch_bounds__(256)
void hgemm_kernel(const uint4* __restrict__ Ah, const uint4* __restrict__ Al,
                  const uint4* __restrict__ Bh, const uint4* __restrict__ Bl,
                  float* __restrict__ C, int N)
{
    extern __shared__ __align__(1024) char sm[];
    const int bm = blockIdx.y * 128, bn = blockIdx.x * 128;

    GemmAcc A;
    gemm_mainloop(Ah, Al, Bh, Bl, bm, bn, sm, A);

    const int wid = threadIdx.x >> 5, lid = threadIdx.x & 31;
    const int wm = wid & 1, wn = wid >> 1;
    const int g = lid >> 2, t = lid & 3;
#pragma unroll
    for (int mt = 0; mt < 4; mt++) {
#pragma unroll
        for (int nt = 0; nt < 4; nt++) {
            const int row0 = bm + wm * 64 + mt * 16 + g;
            const int col0 = bn + wn * 32 + nt * 8 + t * 2;
#pragma unroll
            for (int rh = 0; rh < 2; rh++) {
                const int m = row0 + rh * 8;
                *(float2*)&C[(size_t)m * N + col0] =
                    make_float2(A.c[mt][nt][rh * 2], A.c[mt][nt][rh * 2 + 1]);
            }
        }
    }
}

// ---------------------------------------------------------------------------
// HMMA flash attention, split-bf16, cp.async double-buffered (unchanged).
// Block 256 threads (8 warps), Q-tile 128 (warp = 16 rows), K-tile 64.
// ---------------------------------------------------------------------------
#define FMHA_SMEM (2 * 32768)

__global__ __launch_bounds__(256)
void fmha_kernel(const uint4* __restrict__ Qh4, const uint4* __restrict__ Ql4,
                 const uint4* __restrict__ Kh4, const uint4* __restrict__ Kl4,
                 const uint4* __restrict__ Vh4, const uint4* __restrict__ Vl4,
                 uint32_t* __restrict__ oh, uint32_t* __restrict__ ol)
{
    extern __shared__ __align__(1024) char smf[];
    const uint32_t sb = smem_u32(smf);

    const int tid = threadIdx.x;
    const int wid = tid >> 5, lid = tid & 31;
    const int qt = (int)gridDim.x - 1 - (int)blockIdx.x;   // longest first
    const int h = blockIdx.y, b = blockIdx.z;
    const int kvh = h >> 2;

    const int g = lid >> 2, t = lid & 3;
    const int r8 = lid & 7, sub = lid >> 3;

    // Q fragments: warp covers rows [qt*128 + wid*16, +16)
    const uint32_t* Qh = (const uint32_t*)Qh4;
    const uint32_t* Ql = (const uint32_t*)Ql4;
    const size_t qbase = ((size_t)(b * Hh + h) * Sq) * 32;
    const int row0 = qt * 128 + wid * 16 + g;
    uint32_t qa_h[4][4], qa_l[4][4];
#pragma unroll
    for (int j = 0; j < 4; j++) {
        const size_t b0 = qbase + (size_t)row0 * 32 + j * 8 + t;
        const size_t b1 = b0 + 8 * 32;
        qa_h[j][0] = Qh[b0];     qa_h[j][1] = Qh[b1];
        qa_h[j][2] = Qh[b0 + 4]; qa_h[j][3] = Qh[b1 + 4];
        qa_l[j][0] = Ql[b0];     qa_l[j][1] = Ql[b1];
        qa_l[j][2] = Ql[b0 + 4]; qa_l[j][3] = Ql[b1 + 4];
    }

    const size_t kb4 = ((size_t)(b * HKVq + kvh) * Sq) * 8;

    uint32_t so2[2];
    size_t gk[2];
#pragma unroll
    for (int i = 0; i < 2; i++) {
        const int f = tid + i * 256;
        const int row = f >> 3, c16 = f & 7;
        so2[i] = SWZ((uint32_t)(row * 128 + c16 * 16));
        gk[i] = (size_t)row * 8 + c16;
    }

    auto load_stage = [&](int jt, int st) {
        const uint32_t base = (uint32_t)(st * 32768);
        const size_t gbase = kb4 + (size_t)jt * 64 * 8;
#pragma unroll
        for (int i = 0; i < 2; i++) {
            const size_t gi = gbase + gk[i];
            cp16(sb + base + 0     + so2[i], Kh4 + gi);
            cp16(sb + base + 8192  + so2[i], Kl4 + gi);
            cp16(sb + base + 16384 + so2[i], Vh4 + gi);
            cp16(sb + base + 24576 + so2[i], Vl4 + gi);
        }
    };

    float m0 = -1e30f, m1 = -1e30f, l0 = 0.f, l1 = 0.f;
    float o_[8][4];
#pragma unroll
    for (int i = 0; i < 8; i++)
#pragma unroll
        for (int k = 0; k < 4; k++) o_[i][k] = 0.f;

    const int jtmax = 2 * qt + 1;

    load_stage(0, 0);
    CP_COMMIT();

    for (int jt = 0; jt <= jtmax; jt++) {
        if (jt < jtmax) {
            load_stage(jt + 1, (jt + 1) & 1);
            CP_COMMIT();
            CP_WAIT1();
        } else {
            CP_WAIT0();
        }
        __syncthreads();

        const uint32_t base = sb + (uint32_t)((jt & 1) * 32768);
        const uint32_t skh = base, skl = base + 8192;
        const uint32_t svh = base + 16384, svl = base + 24576;

        // ---- S = Q K^T ----
        float s[8][4];
#pragma unroll
        for (int i = 0; i < 8; i++)
#pragma unroll
            for (int k = 0; k < 4; k++) s[i][k] = 0.f;

#pragma unroll
        for (int j = 0; j < 4; j++) {
#pragma unroll
            for (int nb = 0; nb < 4; nb++) {
                const int row = nb * 16 + r8 + ((sub >> 1) << 3);
                const uint32_t colb = (uint32_t)(j * 32 + ((sub & 1) << 4));
                const uint32_t ad = (uint32_t)(row * 128) + (colb ^ (uint32_t)((row & 7) << 4));
                uint32_t kh[4], kl[4];
                ldsm_x4(kh, skh + ad);
                ldsm_x4(kl, skl + ad);
#pragma unroll
                for (int hh = 0; hh < 2; hh++) {
                    float* acc = s[nb * 2 + hh];
                    mma_bf16(acc, qa_h[j], kh[hh * 2], kh[hh * 2 + 1]);
                    mma_bf16(acc, qa_h[j], kl[hh * 2], kl[hh * 2 + 1]);
                    mma_bf16(acc, qa_l[j], kh[hh * 2], kh[hh * 2 + 1]);
                }
            }
        }

        // ---- causal mask (near-diagonal tiles; also zeroes fully-masked) ----
        if (jt * 64 + 63 > row0) {
#pragma unroll
            for (int nt = 0; nt < 8; nt++) {
                const int col = jt * 64 + nt * 8 + t * 2;
                if (col     > row0)     s[nt][0] = -1e30f;
                if (col + 1 > row0)     s[nt][1] = -1e30f;
                if (col     > row0 + 8) s[nt][2] = -1e30f;
                if (col + 1 > row0 + 8) s[nt][3] = -1e30f;
            }
        }

        // ---- online softmax ----
        float mx0 = -1e30f, mx1 = -1e30f;
#pragma unroll
        for (int nt = 0; nt < 8; nt++) {
            mx0 = fmaxf(mx0, fmaxf(s[nt][0], s[nt][1]));
            mx1 = fmaxf(mx1, fmaxf(s[nt][2], s[nt][3]));
        }
        mx0 = fmaxf(mx0, __shfl_xor_sync(0xffffffffu, mx0, 1));
        mx0 = fmaxf(mx0, __shfl_xor_sync(0xffffffffu, mx0, 2));
        mx1 = fmaxf(mx1, __shfl_xor_sync(0xffffffffu, mx1, 1));
        mx1 = fmaxf(mx1, __shfl_xor_sync(0xffffffffu, mx1, 2));

        const float m0n = fmaxf(m0, mx0), m1n = fmaxf(m1, mx1);
        const float f0 = __expf(m0 - m0n), f1 = __expf(m1 - m1n);

        float sum0 = 0.f, sum1 = 0.f;
#pragma unroll
        for (int nt = 0; nt < 8; nt++) {
            s[nt][0] = __expf(s[nt][0] - m0n); sum0 += s[nt][0];
            s[nt][1] = __expf(s[nt][1] - m0n); sum0 += s[nt][1];
            s[nt][2] = __expf(s[nt][2] - m1n); sum1 += s[nt][2];
            s[nt][3] = __expf(s[nt][3] - m1n); sum1 += s[nt][3];
        }
        sum0 += __shfl_xor_sync(0xffffffffu, sum0, 1);
        sum0 += __shfl_xor_sync(0xffffffffu, sum0, 2);
        sum1 += __shfl_xor_sync(0xffffffffu, sum1, 1);
        sum1 += __shfl_xor_sync(0xffffffffu, sum1, 2);

        l0 = l0 * f0 + sum0;
        l1 = l1 * f1 + sum1;
        m0 = m0n; m1 = m1n;
#pragma unroll
        for (int dt = 0; dt < 8; dt++) {
            o_[dt][0] *= f0; o_[dt][1] *= f0;
            o_[dt][2] *= f1; o_[dt][3] *= f1;
        }

        // ---- pack P fragments (hi/lo) ----
        uint32_t ph[4][4], pl[4][4];
#pragma unroll
        for (int j = 0; j < 4; j++) {
            split2(s[2 * j][0],     s[2 * j][1],     ph[j][0], pl[j][0]);
            split2(s[2 * j][2],     s[2 * j][3],     ph[j][1], pl[j][1]);
            split2(s[2 * j + 1][0], s[2 * j + 1][1], ph[j][2], pl[j][2]);
            split2(s[2 * j + 1][2], s[2 * j + 1][3], ph[j][3], pl[j][3]);
        }

        // ---- O += P V ----
#pragma unroll
        for (int j = 0; j < 4; j++) {
#pragma unroll
            for (int db = 0; db < 4; db++) {
                const int row = 16 * j + r8 + ((sub & 1) << 3);
                const uint32_t colb = (uint32_t)(db * 32 + ((sub >> 1) << 4));
                const uint32_t ad = (uint32_t)(row * 128) + (colb ^ (uint32_t)((row & 7) << 4));
                uint32_t vh[4], vl[4];
                ldsm_x4_t(vh, svh + ad);
                ldsm_x4_t(vl, svl + ad);
#pragma unroll
                for (int hh = 0; hh < 2; hh++) {
                    float* acc = o_[db * 2 + hh];
                    mma_bf16(acc, ph[j], vh[hh * 2], vh[hh * 2 + 1]);
                    mma_bf16(acc, ph[j], vl[hh * 2], vl[hh * 2 + 1]);
                    mma_bf16(acc, pl[j], vh[hh * 2], vh[hh * 2 + 1]);
                }
            }
        }
        __syncthreads();
    }

    // ---- epilogue: O /= l, split to bf16 hi/lo, write [B*S, 2048] ----
    const float inv0 = 1.f / l0, inv1 = 1.f / l1;
    const size_t r0u = ((size_t)b * Sq + row0) * 1024 + h * 32;
    const size_t r1u = r0u + (size_t)8 * 1024;
#pragma unroll
    for (int dt = 0; dt < 8; dt++) {
        const int du = (dt * 8 + t * 2) >> 1;
        uint32_t hh, ll;
        split2(o_[dt][0] * inv0, o_[dt][1] * inv0, hh, ll);
        oh[r0u + du] = hh; ol[r0u + du] = ll;
        split2(o_[dt][2] * inv1, o_[dt][3] * inv1, hh, ll);
        oh[r1u + du] = hh; ol[r1u + du] = ll;
    }
}

// ---------------------------------------------------------------------------
// Launch
// ---------------------------------------------------------------------------
extern "C" void kernel_launch(void* const* d_in, const int* in_sizes, int n_in,
                              void* d_out, int out_size)
{
    const float* hidden = (const float*)d_in[0];
    const float* cosb   = (const float*)d_in[1];
    const float* sinb   = (const float*)d_in[2];
    // d_in[3] = attention_mask (pure causal; not needed)
    float* out = (float*)d_out;

    cudaFuncSetAttribute(hgemm_qkv_kernel, cudaFuncAttributeMaxDynamicSharedMemorySize, GEMM_SMEM);
    cudaFuncSetAttribute(hgemm_kernel, cudaFuncAttributeMaxDynamicSharedMemorySize, GEMM_SMEM);
    cudaFuncSetAttribute(fmha_kernel, cudaFuncAttributeMaxDynamicSharedMemorySize, FMHA_SMEM);

    float *qp, *kp, *vp;
    cudaGetSymbolAddress((void**)&qp, g_q);
    cudaGetSymbolAddress((void**)&kp, g_k);
    cudaGetSymbolAddress((void**)&vp, g_v);

    uint4 *hidh, *hidl, *wqh, *wql, *wkh, *wkl, *wvh, *wvl, *woh, *wol, *aoh, *aol;
    cudaGetSymbolAddress((void**)&hidh, g_hid_h); cudaGetSymbolAddress((void**)&hidl, g_hid_l);
    cudaGetSymbolAddress((void**)&wqh,  g_wq_h);  cudaGetSymbolAddress((void**)&wql,  g_wq_l);
    cudaGetSymbolAddress((void**)&wkh,  g_wk_h);  cudaGetSymbolAddress((void**)&wkl,  g_wk_l);
    cudaGetSymbolAddress((void**)&wvh,  g_wv_h);  cudaGetSymbolAddress((void**)&wvl,  g_wv_l);
    cudaGetSymbolAddress((void**)&woh,  g_wo_h);  cudaGetSymbolAddress((void**)&wol,  g_wo_l);
    cudaGetSymbolAddress((void**)&aoh,  g_ao_h);  cudaGetSymbolAddress((void**)&aol,  g_ao_l);

    uint4 *qh, *ql, *kh, *kl, *vh, *vl;
    cudaGetSymbolAddress((void**)&qh, g_qh4); cudaGetSymbolAddress((void**)&ql, g_ql4);
    cudaGetSymbolAddress((void**)&kh, g_kh4); cudaGetSymbolAddress((void**)&kl, g_kl4);
    cudaGetSymbolAddress((void**)&vh, g_vh4); cudaGetSymbolAddress((void**)&vl, g_vl4);

    // Fused input splits (one launch): hidden, Wq, Wk, Wv, Wo
    split5_kernel<<<4608, 256>>>(
        (const float4*)hidden,  (uint2*)hidh, (uint2*)hidl,
        (const float4*)d_in[4], (uint2*)wqh,  (uint2*)wql,
        (const float4*)d_in[5], (uint2*)wkh,  (uint2*)wkl,
        (const float4*)d_in[6], (uint2*)wvh,  (uint2*)wvl,
        (const float4*)d_in[7], (uint2*)woh,  (uint2*)wol);

    // Fused QKV projection (one launch) -> [B,H,S,D] fp32
    hgemm_qkv_kernel<<<dim3(24, 32), 256, GEMM_SMEM>>>(
        hidh, hidl, wqh, wql, wkh, wkl, wvh, wvl, qp, kp, vp);

    // Fused RoPE(Q)+RoPE(K)+split(V) (one launch)
    postqkv_kernel<<<20992, 256>>>(qp, kp, (const float4*)vp, cosb, sinb,
                                   (__nv_bfloat16*)qh, (__nv_bfloat16*)ql,
                                   (__nv_bfloat16*)kh, (__nv_bfloat16*)kl,
                                   (uint2*)vh, (uint2*)vl);

    // HMMA flash attention (Q-tile 128, reversed order) -> bf16 hi/lo attn out
    fmha_kernel<<<dim3(16, Hh, Bq), 256, FMHA_SMEM>>>(qh, ql, kh, kl, vh, vl,
                                                      (uint32_t*)aoh, (uint32_t*)aol);

    // Output projection on tensor cores -> d_out
    hgemm_kernel<<<dim3(16, 32), 256, GEMM_SMEM>>>(aoh, aol, woh, wol, out, 2048);
}